// round 11
// baseline (speedup 1.0000x reference)
#include <cuda_runtime.h>
#include <cstddef>

// Problem constants
#define B_  64
#define L_  2048
#define C_  20
#define H1_ 384
#define H2_ 16
#define F_  20

// Output layout (flattened tuple, reference order):
// x_mid (B,L,F) | x_out (B,L,F) | h1f (B,H1) | h2f (B,H2) | h3f (B,F)
#define XMID_OFF 0
#define XOUT_OFF (B_*L_*F_)
#define H1F_OFF  (2*B_*L_*F_)
#define H2F_OFF  (H1F_OFF + B_*H1_)
#define H3F_OFF  (H2F_OFF + B_*H2_)

// Scratch (device globals: allocation-free rule)
__device__ float g_h1[B_*H1_];
__device__ float g_y1[(size_t)B_*L_*H1_];   // 201 MB
__device__ unsigned g_bar_cnt;              // returns to 0 each launch
__device__ unsigned g_bar_gen;              // monotonic across launches

#define NBLK1 128   // GRU1 grid: 128 CTAs, 3 hidden units each

// ---------------------------------------------------------------------------
// Kernel 1: GRU1 (C=20 -> H1=384), persistent, grid-barrier per step.
// Each CTA owns 3 hidden units (9 gate rows of Whh1, SMEM-resident).
// 8 warps x 8 batches; per warp: K split over 32 lanes, 72 accumulators/lane.
// ---------------------------------------------------------------------------
__global__ __launch_bounds__(256, 1) void gru1_kernel(
    const float* __restrict__ x, const float* __restrict__ h1_in,
    const float* __restrict__ Wih1, const float* __restrict__ Whh1,
    const float* __restrict__ bih1, const float* __restrict__ bhh1,
    float* __restrict__ out_h1f)
{
    extern __shared__ float sm[];
    float* h_s  = sm;                          // 64*384 = 24576
    float* Wh_s = h_s  + B_*H1_;               // 9*384  = 3456
    float* xs   = Wh_s + 9*H1_;                // 64*20  = 1280
    float* Wi_s = xs   + B_*C_;                // 9*20   = 180
    float* bi_s = Wi_s + 9*C_;                 // 12
    float* bh_s = bi_s + 12;                   // 12
    float* red  = bh_s + 12;                   // 8*72   = 576

    const int tid  = threadIdx.x;
    const int lane = tid & 31;
    const int w    = tid >> 5;
    const int u0   = blockIdx.x * 3;           // first hidden unit of this CTA
    const int b0   = w * 8;                    // first batch of this warp

    // Load weights for our 9 gate rows (row lr = g*3 + u, g in {r,z,n})
    for (int i = tid; i < 9*H1_; i += 256) {
        int lr = i / H1_, k = i % H1_;
        int g = lr / 3, u = lr % 3;
        Wh_s[i] = Whh1[(size_t)(g*H1_ + u0 + u)*H1_ + k];
    }
    for (int i = tid; i < 9*C_; i += 256) {
        int lr = i / C_, c = i % C_;
        int g = lr / 3, u = lr % 3;
        Wi_s[i] = Wih1[(g*H1_ + u0 + u)*C_ + c];
    }
    if (tid < 9) {
        int g = tid / 3, u = tid % 3;
        bi_s[tid] = bih1[g*H1_ + u0 + u];
        bh_s[tid] = bhh1[g*H1_ + u0 + u];
    }

    // Barrier generation base (stable: previous launch fully done, nobody
    // writes g_bar_gen until all CTAs of this launch arrive at barrier 0).
    const unsigned base = *(volatile unsigned*)&g_bar_gen;

    for (int t = 0; t < L_; t++) {
        // ---- broadcast load of full h state (L2, bypass L1) ----
        const float* hsrc = (t == 0) ? h1_in : g_h1;
        {
            const float4* s4 = (const float4*)hsrc;
            float4* d4 = (float4*)h_s;
            #pragma unroll 1
            for (int i = tid; i < (B_*H1_)/4; i += 256) d4[i] = __ldcg(s4 + i);
        }
        // ---- x_t (64x20) ----
        for (int i = tid; i < B_*C_/4; i += 256) {
            int b = i / 5, c4 = i % 5;
            ((float4*)xs)[b*5 + c4] =
                __ldg((const float4*)(x + (size_t)b*L_*C_ + (size_t)t*C_) + c4);
        }
        __syncthreads();

        // ---- main recurrent GEMM slice: 9 rows x 8 batches, K=384 ----
        float acc[72];
        #pragma unroll
        for (int i = 0; i < 72; i++) acc[i] = 0.f;

        #pragma unroll 1
        for (int kk = 0; kk < 12; kk++) {
            int k = (kk << 5) + lane;
            float wv[9];
            #pragma unroll
            for (int r = 0; r < 9; r++) wv[r] = Wh_s[r*H1_ + k];
            #pragma unroll
            for (int j = 0; j < 8; j++) {
                float hv = h_s[(b0 + j)*H1_ + k];
                #pragma unroll
                for (int r = 0; r < 9; r++)
                    acc[r*8 + j] = fmaf(wv[r], hv, acc[r*8 + j]);
            }
        }
        // butterfly reduce across lanes (every lane ends with all 72 sums)
        #pragma unroll
        for (int s = 16; s > 0; s >>= 1) {
            #pragma unroll
            for (int i = 0; i < 72; i++)
                acc[i] += __shfl_xor_sync(0xffffffffu, acc[i], s);
        }
        // lane 0 spills reduced sums (constant reg indices) for epilogue lanes
        if (lane == 0) {
            #pragma unroll
            for (int i = 0; i < 72; i++) red[w*72 + i] = acc[i];
        }
        __syncwarp();

        // ---- epilogue: 24 lanes = 8 batches x 3 hidden units ----
        if (lane < 24) {
            int bl = lane & 7;
            int u  = lane >> 3;          // 0..2
            int b  = b0 + bl;
            // input projection (K=20)
            float xr = bi_s[u], xz = bi_s[3+u], xn = bi_s[6+u];
            #pragma unroll
            for (int c = 0; c < C_; c++) {
                float xv = xs[b*C_ + c];
                xr = fmaf(Wi_s[u*C_ + c],       xv, xr);
                xz = fmaf(Wi_s[(3+u)*C_ + c],   xv, xz);
                xn = fmaf(Wi_s[(6+u)*C_ + c],   xv, xn);
            }
            float ghr = red[w*72 + (u  )*8 + bl] + bh_s[u];
            float ghz = red[w*72 + (3+u)*8 + bl] + bh_s[3+u];
            float ghn = red[w*72 + (6+u)*8 + bl] + bh_s[6+u];
            float rg = 1.f / (1.f + __expf(-(xr + ghr)));
            float zg = 1.f / (1.f + __expf(-(xz + ghz)));
            float ng = tanhf(xn + rg * ghn);
            float hold = h_s[b*H1_ + u0 + u];
            float hn = (1.f - zg) * ng + zg * hold;
            g_h1[b*H1_ + u0 + u] = hn;
            g_y1[((size_t)b*L_ + t)*H1_ + u0 + u] = hn;
            if (t == L_-1) out_h1f[b*H1_ + u0 + u] = hn;
        }

        // ---- grid barrier (sense = monotonic generation counter) ----
        __threadfence();
        __syncthreads();
        if (tid == 0) {
            unsigned target = base + (unsigned)(t + 1);
            unsigned a = atomicAdd(&g_bar_cnt, 1u);
            if (a == NBLK1 - 1) {
                g_bar_cnt = 0;
                __threadfence();
                *(volatile unsigned*)&g_bar_gen = target;
            } else {
                while (*(volatile unsigned*)&g_bar_gen - base < (unsigned)(t + 1))
                    __nanosleep(16);
            }
        }
        __syncthreads();
    }
}

// ---------------------------------------------------------------------------
// Kernel 2: GRU2 (H1=384 -> H2=16) + ReLU + dual-FC (== 2*tanh(fc)) -> x_mid.
// One CTA per batch element; all weights SMEM-resident; y1 prefetched 1 step.
// ---------------------------------------------------------------------------
__global__ __launch_bounds__(256, 1) void gru2_kernel(
    const float* __restrict__ h2_in,
    const float* __restrict__ Wih2, const float* __restrict__ Whh2,
    const float* __restrict__ bih2, const float* __restrict__ bhh2,
    const float* __restrict__ Wfc,  const float* __restrict__ bfc,
    float* __restrict__ out)
{
    extern __shared__ float sm[];
    float* W2  = sm;                 // 48*384 = 18432
    float* Wh  = W2  + 48*H1_;       // 48*16  = 768
    float* Wf  = Wh  + 48*H2_;       // 20*16  = 320
    float* bi  = Wf  + F_*H2_;       // 48
    float* bh  = bi  + 48;           // 48
    float* bf  = bh  + 48;           // 20
    float* ys  = bf  + 20;           // 2*384  = 768 (double buffer)
    float* ihp = ys  + 2*H1_;        // 48
    float* h2s = ihp + 48;           // 16
    float* y2s = h2s + 16;           // 16

    const int tid = threadIdx.x, lane = tid & 31, w = tid >> 5;
    const int b = blockIdx.x;

    for (int i = tid; i < 48*H1_; i += 256) W2[i] = Wih2[i];
    for (int i = tid; i < 48*H2_; i += 256) Wh[i] = Whh2[i];
    for (int i = tid; i < F_*H2_; i += 256) Wf[i] = Wfc[i];
    if (tid < 48) { bi[tid] = bih2[tid]; bh[tid] = bhh2[tid]; }
    if (tid < 20) bf[tid] = bfc[tid];
    if (tid < 16) h2s[tid] = h2_in[b*H2_ + tid];

    const float* y1p = g_y1 + (size_t)b*L_*H1_;
    for (int i = tid; i < 96; i += 256)
        ((float4*)ys)[i] = __ldg((const float4*)y1p + i);
    __syncthreads();

    const int row0 = w * 6;
    for (int t = 0; t < L_; t++) {
        float* cur = ys + (t & 1) * H1_;
        float* nxt = ys + ((t + 1) & 1) * H1_;
        float4 pf;
        bool dopf = (tid < 96) && (t + 1 < L_);
        if (dopf) pf = __ldg((const float4*)(y1p + (size_t)(t + 1)*H1_) + tid);

        // input projection: 6 rows/warp, K split over lanes
        float acc[6] = {0,0,0,0,0,0};
        #pragma unroll 1
        for (int kk = 0; kk < 12; kk++) {
            int k = (kk << 5) + lane;
            float yv = cur[k];
            #pragma unroll
            for (int r = 0; r < 6; r++)
                acc[r] = fmaf(W2[(row0 + r)*H1_ + k], yv, acc[r]);
        }
        #pragma unroll
        for (int s = 16; s > 0; s >>= 1) {
            #pragma unroll
            for (int r = 0; r < 6; r++)
                acc[r] += __shfl_xor_sync(0xffffffffu, acc[r], s);
        }
        #pragma unroll
        for (int r = 0; r < 6; r++)
            if (lane == r) ihp[row0 + r] = acc[r] + bi[row0 + r];
        if (dopf) ((float4*)nxt)[tid] = pf;
        __syncthreads();

        if (w == 0) {
            float hn = 0.f;
            if (lane < 16) {
                float ghr = bh[lane], ghz = bh[16+lane], ghn = bh[32+lane];
                #pragma unroll
                for (int k = 0; k < 16; k++) {
                    float hv = h2s[k];
                    ghr = fmaf(Wh[lane*16 + k],      hv, ghr);
                    ghz = fmaf(Wh[(16+lane)*16 + k], hv, ghz);
                    ghn = fmaf(Wh[(32+lane)*16 + k], hv, ghn);
                }
                float rg = 1.f / (1.f + __expf(-(ihp[lane] + ghr)));
                float zg = 1.f / (1.f + __expf(-(ihp[16+lane] + ghz)));
                float ng = tanhf(ihp[32+lane] + rg * ghn);
                hn = (1.f - zg) * ng + zg * h2s[lane];
            }
            __syncwarp();
            if (lane < 16) { h2s[lane] = hn; y2s[lane] = fmaxf(hn, 0.f); }
            __syncwarp();
            if (lane < 20) {
                float a = bf[lane];
                #pragma unroll
                for (int k = 0; k < 16; k++)
                    a = fmaf(Wf[lane*16 + k], y2s[k], a);
                out[XMID_OFF + ((size_t)b*L_ + t)*F_ + lane] = 2.f * tanhf(a);
            }
            if (t == L_-1 && lane < 16) out[H2F_OFF + b*H2_ + lane] = hn;
        }
        __syncthreads();
    }
}

// ---------------------------------------------------------------------------
// Kernel 3: GRU3 (F=20 -> F=20) on time-reversed x_mid, x_out = tanh(y3).
// One warp per batch element.
// ---------------------------------------------------------------------------
__global__ __launch_bounds__(32, 1) void gru3_kernel(
    const float* __restrict__ h3_in,
    const float* __restrict__ Wih3, const float* __restrict__ Whh3,
    const float* __restrict__ bih3, const float* __restrict__ bhh3,
    float* __restrict__ out)
{
    __shared__ float Wi[60*20], Wh[60*20];
    __shared__ float bi[60], bh[60], as_[60], gs_[60], h3s[20];
    __shared__ __align__(16) float ins[2][20];

    const int lane = threadIdx.x;
    const int b = blockIdx.x;

    for (int i = lane; i < 60*20; i += 32) { Wi[i] = Wih3[i]; Wh[i] = Whh3[i]; }
    for (int i = lane; i < 60;    i += 32) { bi[i] = bih3[i]; bh[i] = bhh3[i]; }
    if (lane < 20) h3s[lane] = h3_in[b*F_ + lane];

    const float* xmid = out + XMID_OFF + (size_t)b*L_*F_;
    if (lane < 5)
        ((float4*)ins[0])[lane] = *((const float4*)(xmid + (size_t)(L_-1)*F_) + lane);
    __syncwarp();

    for (int t = 0; t < L_; t++) {
        float* in = ins[t & 1];
        float4 pf;
        bool dopf = (lane < 5) && (t + 1 < L_);
        if (dopf)
            pf = *((const float4*)(xmid + (size_t)(L_-2-t)*F_) + lane);

        // rows: lane (0..31) and lane+32 (when <60)
        const int r1 = lane + 32;
        const bool has1 = (r1 < 60);
        float a0 = bi[lane], g0 = bh[lane], a1 = 0.f, g1 = 0.f;
        if (has1) { a1 = bi[r1]; g1 = bh[r1]; }
        #pragma unroll
        for (int k = 0; k < 20; k++) {
            float iv = in[k], hv = h3s[k];
            a0 = fmaf(Wi[lane*20 + k], iv, a0);
            g0 = fmaf(Wh[lane*20 + k], hv, g0);
            if (has1) {
                a1 = fmaf(Wi[r1*20 + k], iv, a1);
                g1 = fmaf(Wh[r1*20 + k], hv, g1);
            }
        }
        as_[lane] = a0; gs_[lane] = g0;
        if (has1) { as_[r1] = a1; gs_[r1] = g1; }
        __syncwarp();

        float hn = 0.f;
        if (lane < 20) {
            float rg = 1.f / (1.f + __expf(-(as_[lane] + gs_[lane])));
            float zg = 1.f / (1.f + __expf(-(as_[20+lane] + gs_[20+lane])));
            float ng = tanhf(as_[40+lane] + rg * gs_[40+lane]);
            hn = (1.f - zg) * ng + zg * h3s[lane];
        }
        __syncwarp();
        if (lane < 20) {
            h3s[lane] = hn;
            out[XOUT_OFF + ((size_t)b*L_ + t)*F_ + lane] = tanhf(hn);
        }
        if (dopf) ((float4*)ins[(t + 1) & 1])[lane] = pf;
        __syncwarp();
    }
    if (lane < 20) out[H3F_OFF + b*F_ + lane] = h3s[lane];
}

// ---------------------------------------------------------------------------
extern "C" void kernel_launch(void* const* d_in, const int* in_sizes, int n_in,
                              void* d_out, int out_size)
{
    const float* x    = (const float*)d_in[0];
    const float* h1   = (const float*)d_in[1];
    const float* h2   = (const float*)d_in[2];
    const float* h3   = (const float*)d_in[3];
    const float* Wih1 = (const float*)d_in[4];
    const float* Whh1 = (const float*)d_in[5];
    const float* bih1 = (const float*)d_in[6];
    const float* bhh1 = (const float*)d_in[7];
    const float* Wih2 = (const float*)d_in[8];
    const float* Whh2 = (const float*)d_in[9];
    const float* bih2 = (const float*)d_in[10];
    const float* bhh2 = (const float*)d_in[11];
    const float* Wih3 = (const float*)d_in[12];
    const float* Whh3 = (const float*)d_in[13];
    const float* bih3 = (const float*)d_in[14];
    const float* bhh3 = (const float*)d_in[15];
    const float* Wfc  = (const float*)d_in[16];
    const float* bfc  = (const float*)d_in[17];
    float* out = (float*)d_out;

    const int SMEM1 = (B_*H1_ + 9*H1_ + B_*C_ + 9*C_ + 12 + 12 + 8*72) * 4;
    const int SMEM2 = (48*H1_ + 48*H2_ + F_*H2_ + 48 + 48 + 20 + 2*H1_ + 48 + 16 + 16) * 4;
    cudaFuncSetAttribute(gru1_kernel, cudaFuncAttributeMaxDynamicSharedMemorySize, SMEM1);
    cudaFuncSetAttribute(gru2_kernel, cudaFuncAttributeMaxDynamicSharedMemorySize, SMEM2);

    gru1_kernel<<<NBLK1, 256, SMEM1>>>(x, h1, Wih1, Whh1, bih1, bhh1, out + H1F_OFF);
    gru2_kernel<<<B_, 256, SMEM2>>>(h2, Wih2, Whh2, bih2, bhh2, Wfc, bfc, out);
    gru3_kernel<<<B_, 32>>>(h3, Wih3, Whh3, bih3, bhh3, out);
}

// round 12
// speedup vs baseline: 1.6348x; 1.6348x over previous
#include <cuda_runtime.h>
#include <cstddef>

// Problem constants
#define B_  64
#define L_  2048
#define C_  20
#define H1_ 384
#define H2_ 16
#define F_  20

// Output layout (flattened tuple, reference order):
// x_mid (B,L,F) | x_out (B,L,F) | h1f (B,H1) | h2f (B,H2) | h3f (B,F)
#define XMID_OFF 0
#define XOUT_OFF (B_*L_*F_)
#define H1F_OFF  (2*B_*L_*F_)
#define H2F_OFF  (H1F_OFF + B_*H1_)
#define H3F_OFF  (H2F_OFF + B_*H2_)

// Scratch (device globals: allocation-free rule)
__device__ float g_h1[B_*H1_];
__device__ float g_y1[(size_t)B_*L_*H1_];   // 201 MB
__device__ unsigned g_bar_cnt;              // returns to 0 each launch
__device__ unsigned g_bar_gen;              // monotonic across launches

// GRU1 partition: 32 row-groups x 4 batch-groups = 128 CTAs.
// Each CTA: 12 hidden units (36 gate rows) x 16 batches, weights SMEM-resident.
#define NBLK1 128
#define GR_   32
#define GB_   4
#define UPC_  12     // units per CTA
#define RPC_  36     // gate rows per CTA (3*UPC)
#define BPC_  16     // batches per CTA
// SMEM strides (floats), chosen for conflict-free LDS.128:
//  k is stored in 4 chunks of 96 (+4 pad) -> chunk stride SK=100
//  batch stride SB=420, weight row stride WROW=420
#define SK_   100
#define SB_   420
#define WROW_ 420

// ---------------------------------------------------------------------------
// Kernel 1: GRU1 (C=20 -> H1=384), persistent, grid-barrier per step.
// Warp tile: 9 rows x 8 batches, K split over 4 lane-groups (kq), 9 acc/lane.
// ---------------------------------------------------------------------------
__global__ __launch_bounds__(256, 1) void gru1_kernel(
    const float* __restrict__ x, const float* __restrict__ h1_in,
    const float* __restrict__ Wih1, const float* __restrict__ Whh1,
    const float* __restrict__ bih1, const float* __restrict__ bhh1,
    float* __restrict__ out_h1f)
{
    extern __shared__ float sm[];
    float* h_s  = sm;                       // BPC*SB  = 6720
    float* Wh_s = h_s  + BPC_*SB_;          // RPC*WROW= 15120
    float* xs   = Wh_s + RPC_*WROW_;        // BPC*20  = 320
    float* Wi_s = xs   + BPC_*C_;           // RPC*20  = 720
    float* bi_s = Wi_s + RPC_*C_;           // 36
    float* bh_s = bi_s + RPC_;              // 36
    float* red  = bh_s + RPC_;              // 8*72 = 576

    const int tid  = threadIdx.x;
    const int lane = tid & 31;
    const int w    = tid >> 5;
    const int rg   = blockIdx.x & (GR_-1);     // row group 0..31
    const int bg   = blockIdx.x >> 5;          // batch group 0..3
    const int u0   = rg * UPC_;                // first global hidden unit
    const int b0c  = bg * BPC_;                // first global batch

    // warp tiling: 4 row-subgroups x 2 batch-subgroups
    const int rgrp = w >> 1;                   // 0..3 -> units rgrp*3..+2
    const int bgrp = w & 1;                    // 0..1 -> batches bgrp*8..+7
    const int kq   = lane >> 3;                // k quarter 0..3 (96 k each)
    const int bl   = lane & 7;                 // batch within subgroup
    const int bL   = bgrp*8 + bl;              // local batch 0..15

    // ---- load recurrent weights into SMEM (chunked-k layout) ----
    for (int i = tid; i < RPC_*H1_; i += 256) {
        int lr = i / H1_, k = i % H1_;
        int g = lr / UPC_, ul = lr % UPC_;
        Wh_s[lr*WROW_ + (k/96)*SK_ + (k%96)] =
            Whh1[(size_t)(g*H1_ + u0 + ul)*H1_ + k];
    }
    for (int i = tid; i < RPC_*C_; i += 256) {
        int lr = i / C_, c = i % C_;
        int g = lr / UPC_, ul = lr % UPC_;
        Wi_s[i] = Wih1[(g*H1_ + u0 + ul)*C_ + c];
    }
    if (tid < RPC_) {
        int g = tid / UPC_, ul = tid % UPC_;
        bi_s[tid] = bih1[g*H1_ + u0 + ul];
        bh_s[tid] = bhh1[g*H1_ + u0 + ul];
    }

    // Barrier generation base (stable: nobody writes g_bar_gen until all
    // CTAs of this launch have arrived at barrier 0).
    const unsigned base = *(volatile unsigned*)&g_bar_gen;

    // per-lane base pointers for the GEMM
    const float* hb = h_s  + bL*SB_ + kq*SK_;
    const float* wb = Wh_s + (rgrp*3)*WROW_ + kq*SK_;

    for (int t = 0; t < L_; t++) {
        // ---- load h state for our 16 batches (L2, bypass L1) ----
        {
            const float4* s4 = (t == 0)
                ? (const float4*)(h1_in + b0c*H1_)
                : (const float4*)(g_h1  + b0c*H1_);
            #pragma unroll 1
            for (int i4 = tid; i4 < BPC_*(H1_/4); i4 += 256) {
                int b = i4 / 96, k4 = i4 % 96;
                float4 v = (t == 0) ? __ldg(s4 + i4) : __ldcg(s4 + i4);
                *((float4*)h_s + (size_t)b*(SB_/4) + (k4/24)*(SK_/4) + (k4%24)) = v;
            }
        }
        // ---- x_t for our batches (16 x 20) ----
        if (tid < BPC_*5) {
            int b = tid / 5, c4 = tid % 5;
            ((float4*)(xs + b*C_))[c4] =
                __ldg((const float4*)(x + ((size_t)(b0c + b)*L_ + t)*C_) + c4);
        }
        __syncthreads();

        // ---- recurrent GEMM: 9 rows x 8 batches per warp, K/4 per lane ----
        float acc[9];
        #pragma unroll
        for (int r = 0; r < 9; r++) acc[r] = 0.f;

        #pragma unroll 8
        for (int j = 0; j < 24; j++) {
            const float4 h4 = *(const float4*)(hb + 4*j);
            #pragma unroll
            for (int g = 0; g < 3; g++) {
                #pragma unroll
                for (int u = 0; u < 3; u++) {
                    const float4 w4 = *(const float4*)(wb + (g*UPC_ + u)*WROW_ + 4*j);
                    const int r = g*3 + u;
                    acc[r] = fmaf(w4.x, h4.x, acc[r]);
                    acc[r] = fmaf(w4.y, h4.y, acc[r]);
                    acc[r] = fmaf(w4.z, h4.z, acc[r]);
                    acc[r] = fmaf(w4.w, h4.w, acc[r]);
                }
            }
        }
        // reduce over the 4 k-quarters (lane bits 3,4)
        #pragma unroll
        for (int r = 0; r < 9; r++) {
            acc[r] += __shfl_xor_sync(0xffffffffu, acc[r], 8);
            acc[r] += __shfl_xor_sync(0xffffffffu, acc[r], 16);
        }
        if (kq == 0) {
            #pragma unroll
            for (int r = 0; r < 9; r++) red[w*72 + r*8 + bl] = acc[r];
        }
        __syncwarp();

        // ---- epilogue: 24 lanes = 3 units x 8 batches ----
        if (lane < 24) {
            const int u   = lane >> 3;          // 0..2
            const int bl2 = lane & 7;
            const int bL2 = bgrp*8 + bl2;       // local batch
            const int b   = b0c + bL2;          // global batch
            const int ug  = u0 + rgrp*3 + u;    // global hidden unit
            const int lrr = rgrp*3 + u;         // local unit row

            float xr = bi_s[lrr], xz = bi_s[UPC_+lrr], xn = bi_s[2*UPC_+lrr];
            #pragma unroll
            for (int c = 0; c < C_; c++) {
                float xv = xs[bL2*C_ + c];
                xr = fmaf(Wi_s[lrr*C_ + c],            xv, xr);
                xz = fmaf(Wi_s[(UPC_+lrr)*C_ + c],     xv, xz);
                xn = fmaf(Wi_s[(2*UPC_+lrr)*C_ + c],   xv, xn);
            }
            float ghr = red[w*72 + (u  )*8 + bl2] + bh_s[lrr];
            float ghz = red[w*72 + (3+u)*8 + bl2] + bh_s[UPC_+lrr];
            float ghn = red[w*72 + (6+u)*8 + bl2] + bh_s[2*UPC_+lrr];
            float rgt = 1.f / (1.f + __expf(-(xr + ghr)));
            float zgt = 1.f / (1.f + __expf(-(xz + ghz)));
            float ngt = tanhf(xn + rgt * ghn);
            float hold = h_s[bL2*SB_ + (ug/96)*SK_ + (ug%96)];
            float hn = (1.f - zgt) * ngt + zgt * hold;
            g_h1[b*H1_ + ug] = hn;
            g_y1[((size_t)b*L_ + t)*H1_ + ug] = hn;
            if (t == L_-1) out_h1f[b*H1_ + ug] = hn;
        }

        // ---- grid barrier (sense = monotonic generation counter) ----
        __threadfence();
        __syncthreads();
        if (tid == 0) {
            unsigned a = atomicAdd(&g_bar_cnt, 1u);
            if (a == NBLK1 - 1) {
                g_bar_cnt = 0;
                __threadfence();
                *(volatile unsigned*)&g_bar_gen = base + (unsigned)(t + 1);
            } else {
                while (*(volatile unsigned*)&g_bar_gen - base < (unsigned)(t + 1))
                    __nanosleep(32);
            }
        }
        __syncthreads();
    }
}

// ---------------------------------------------------------------------------
// Kernel 2: GRU2 (H1=384 -> H2=16) + ReLU + dual-FC (== 2*tanh(fc)) -> x_mid.
// One CTA per batch element; all weights SMEM-resident; y1 prefetched 1 step.
// ---------------------------------------------------------------------------
__global__ __launch_bounds__(256, 1) void gru2_kernel(
    const float* __restrict__ h2_in,
    const float* __restrict__ Wih2, const float* __restrict__ Whh2,
    const float* __restrict__ bih2, const float* __restrict__ bhh2,
    const float* __restrict__ Wfc,  const float* __restrict__ bfc,
    float* __restrict__ out)
{
    extern __shared__ float sm[];
    float* W2  = sm;                 // 48*384 = 18432
    float* Wh  = W2  + 48*H1_;       // 48*16  = 768
    float* Wf  = Wh  + 48*H2_;       // 20*16  = 320
    float* bi  = Wf  + F_*H2_;       // 48
    float* bh  = bi  + 48;           // 48
    float* bf  = bh  + 48;           // 20
    float* ys  = bf  + 20;           // 2*384  = 768 (double buffer)
    float* ihp = ys  + 2*H1_;        // 48
    float* h2s = ihp + 48;           // 16
    float* y2s = h2s + 16;           // 16

    const int tid = threadIdx.x, lane = tid & 31, w = tid >> 5;
    const int b = blockIdx.x;

    for (int i = tid; i < 48*H1_; i += 256) W2[i] = Wih2[i];
    for (int i = tid; i < 48*H2_; i += 256) Wh[i] = Whh2[i];
    for (int i = tid; i < F_*H2_; i += 256) Wf[i] = Wfc[i];
    if (tid < 48) { bi[tid] = bih2[tid]; bh[tid] = bhh2[tid]; }
    if (tid < 20) bf[tid] = bfc[tid];
    if (tid < 16) h2s[tid] = h2_in[b*H2_ + tid];

    const float* y1p = g_y1 + (size_t)b*L_*H1_;
    for (int i = tid; i < 96; i += 256)
        ((float4*)ys)[i] = __ldg((const float4*)y1p + i);
    __syncthreads();

    const int row0 = w * 6;
    for (int t = 0; t < L_; t++) {
        float* cur = ys + (t & 1) * H1_;
        float* nxt = ys + ((t + 1) & 1) * H1_;
        float4 pf;
        bool dopf = (tid < 96) && (t + 1 < L_);
        if (dopf) pf = __ldg((const float4*)(y1p + (size_t)(t + 1)*H1_) + tid);

        // input projection: 6 rows/warp, K split over lanes
        float acc[6] = {0,0,0,0,0,0};
        #pragma unroll 1
        for (int kk = 0; kk < 12; kk++) {
            int k = (kk << 5) + lane;
            float yv = cur[k];
            #pragma unroll
            for (int r = 0; r < 6; r++)
                acc[r] = fmaf(W2[(row0 + r)*H1_ + k], yv, acc[r]);
        }
        #pragma unroll
        for (int s = 16; s > 0; s >>= 1) {
            #pragma unroll
            for (int r = 0; r < 6; r++)
                acc[r] += __shfl_xor_sync(0xffffffffu, acc[r], s);
        }
        #pragma unroll
        for (int r = 0; r < 6; r++)
            if (lane == r) ihp[row0 + r] = acc[r] + bi[row0 + r];
        if (dopf) ((float4*)nxt)[tid] = pf;
        __syncthreads();

        if (w == 0) {
            float hn = 0.f;
            if (lane < 16) {
                float ghr = bh[lane], ghz = bh[16+lane], ghn = bh[32+lane];
                #pragma unroll
                for (int k = 0; k < 16; k++) {
                    float hv = h2s[k];
                    ghr = fmaf(Wh[lane*16 + k],      hv, ghr);
                    ghz = fmaf(Wh[(16+lane)*16 + k], hv, ghz);
                    ghn = fmaf(Wh[(32+lane)*16 + k], hv, ghn);
                }
                float rg = 1.f / (1.f + __expf(-(ihp[lane] + ghr)));
                float zg = 1.f / (1.f + __expf(-(ihp[16+lane] + ghz)));
                float ng = tanhf(ihp[32+lane] + rg * ghn);
                hn = (1.f - zg) * ng + zg * h2s[lane];
            }
            __syncwarp();
            if (lane < 16) { h2s[lane] = hn; y2s[lane] = fmaxf(hn, 0.f); }
            __syncwarp();
            if (lane < 20) {
                float a = bf[lane];
                #pragma unroll
                for (int k = 0; k < 16; k++)
                    a = fmaf(Wf[lane*16 + k], y2s[k], a);
                out[XMID_OFF + ((size_t)b*L_ + t)*F_ + lane] = 2.f * tanhf(a);
            }
            if (t == L_-1 && lane < 16) out[H2F_OFF + b*H2_ + lane] = hn;
        }
        __syncthreads();
    }
}

// ---------------------------------------------------------------------------
// Kernel 3: GRU3 (F=20 -> F=20) on time-reversed x_mid, x_out = tanh(y3).
// One warp per batch element.
// ---------------------------------------------------------------------------
__global__ __launch_bounds__(32, 1) void gru3_kernel(
    const float* __restrict__ h3_in,
    const float* __restrict__ Wih3, const float* __restrict__ Whh3,
    const float* __restrict__ bih3, const float* __restrict__ bhh3,
    float* __restrict__ out)
{
    __shared__ float Wi[60*20], Wh[60*20];
    __shared__ float bi[60], bh[60], as_[60], gs_[60], h3s[20];
    __shared__ __align__(16) float ins[2][20];

    const int lane = threadIdx.x;
    const int b = blockIdx.x;

    for (int i = lane; i < 60*20; i += 32) { Wi[i] = Wih3[i]; Wh[i] = Whh3[i]; }
    for (int i = lane; i < 60;    i += 32) { bi[i] = bih3[i]; bh[i] = bhh3[i]; }
    if (lane < 20) h3s[lane] = h3_in[b*F_ + lane];

    const float* xmid = out + XMID_OFF + (size_t)b*L_*F_;
    if (lane < 5)
        ((float4*)ins[0])[lane] = *((const float4*)(xmid + (size_t)(L_-1)*F_) + lane);
    __syncwarp();

    for (int t = 0; t < L_; t++) {
        float* in = ins[t & 1];
        float4 pf;
        bool dopf = (lane < 5) && (t + 1 < L_);
        if (dopf)
            pf = *((const float4*)(xmid + (size_t)(L_-2-t)*F_) + lane);

        // rows: lane (0..31) and lane+32 (when <60)
        const int r1 = lane + 32;
        const bool has1 = (r1 < 60);
        float a0 = bi[lane], g0 = bh[lane], a1 = 0.f, g1 = 0.f;
        if (has1) { a1 = bi[r1]; g1 = bh[r1]; }
        #pragma unroll
        for (int k = 0; k < 20; k++) {
            float iv = in[k], hv = h3s[k];
            a0 = fmaf(Wi[lane*20 + k], iv, a0);
            g0 = fmaf(Wh[lane*20 + k], hv, g0);
            if (has1) {
                a1 = fmaf(Wi[r1*20 + k], iv, a1);
                g1 = fmaf(Wh[r1*20 + k], hv, g1);
            }
        }
        as_[lane] = a0; gs_[lane] = g0;
        if (has1) { as_[r1] = a1; gs_[r1] = g1; }
        __syncwarp();

        float hn = 0.f;
        if (lane < 20) {
            float rg = 1.f / (1.f + __expf(-(as_[lane] + gs_[lane])));
            float zg = 1.f / (1.f + __expf(-(as_[20+lane] + gs_[20+lane])));
            float ng = tanhf(as_[40+lane] + rg * gs_[40+lane]);
            hn = (1.f - zg) * ng + zg * h3s[lane];
        }
        __syncwarp();
        if (lane < 20) {
            h3s[lane] = hn;
            out[XOUT_OFF + ((size_t)b*L_ + t)*F_ + lane] = tanhf(hn);
        }
        if (dopf) ((float4*)ins[(t + 1) & 1])[lane] = pf;
        __syncwarp();
    }
    if (lane < 20) out[H3F_OFF + b*F_ + lane] = h3s[lane];
}

// ---------------------------------------------------------------------------
extern "C" void kernel_launch(void* const* d_in, const int* in_sizes, int n_in,
                              void* d_out, int out_size)
{
    const float* x    = (const float*)d_in[0];
    const float* h1   = (const float*)d_in[1];
    const float* h2   = (const float*)d_in[2];
    const float* h3   = (const float*)d_in[3];
    const float* Wih1 = (const float*)d_in[4];
    const float* Whh1 = (const float*)d_in[5];
    const float* bih1 = (const float*)d_in[6];
    const float* bhh1 = (const float*)d_in[7];
    const float* Wih2 = (const float*)d_in[8];
    const float* Whh2 = (const float*)d_in[9];
    const float* bih2 = (const float*)d_in[10];
    const float* bhh2 = (const float*)d_in[11];
    const float* Wih3 = (const float*)d_in[12];
    const float* Whh3 = (const float*)d_in[13];
    const float* bih3 = (const float*)d_in[14];
    const float* bhh3 = (const float*)d_in[15];
    const float* Wfc  = (const float*)d_in[16];
    const float* bfc  = (const float*)d_in[17];
    float* out = (float*)d_out;

    const int SMEM1 = (BPC_*SB_ + RPC_*WROW_ + BPC_*C_ + RPC_*C_ + RPC_ + RPC_ + 8*72) * 4;
    const int SMEM2 = (48*H1_ + 48*H2_ + F_*H2_ + 48 + 48 + 20 + 2*H1_ + 48 + 16 + 16) * 4;
    cudaFuncSetAttribute(gru1_kernel, cudaFuncAttributeMaxDynamicSharedMemorySize, SMEM1);
    cudaFuncSetAttribute(gru2_kernel, cudaFuncAttributeMaxDynamicSharedMemorySize, SMEM2);

    gru1_kernel<<<NBLK1, 256, SMEM1>>>(x, h1, Wih1, Whh1, bih1, bhh1, out + H1F_OFF);
    gru2_kernel<<<B_, 256, SMEM2>>>(h2, Wih2, Whh2, bih2, bhh2, Wfc, bfc, out);
    gru3_kernel<<<B_, 32>>>(h3, Wih3, Whh3, bih3, bhh3, out);
}

// round 13
// speedup vs baseline: 1.8764x; 1.1478x over previous
#include <cuda_runtime.h>
#include <cstddef>

// Problem constants
#define B_  64
#define L_  2048
#define C_  20
#define H1_ 384
#define H2_ 16
#define F_  20

// Output layout (flattened tuple, reference order):
// x_mid (B,L,F) | x_out (B,L,F) | h1f (B,H1) | h2f (B,H2) | h3f (B,F)
#define XMID_OFF 0
#define XOUT_OFF (B_*L_*F_)
#define H1F_OFF  (2*B_*L_*F_)
#define H2F_OFF  (H1F_OFF + B_*H1_)
#define H3F_OFF  (H2F_OFF + B_*H2_)

// Scratch (device globals: allocation-free rule)
__device__ float g_h1[B_*H1_];
__device__ float g_y1[(size_t)B_*L_*H1_];   // 201 MB
__device__ unsigned g_bar_cnt[8];           // per-batch-group, returns to 0
__device__ unsigned g_bar_gen[8];           // monotonic across launches

// GRU1 partition: 16 row-groups x 8 batch-groups = 128 CTAs.
// Each CTA: 24 hidden units (72 gate rows, SMEM-resident) x 8 batches.
// 512 threads = 16 warps = 8 rgrp x 2 khalf. Warp tile: 9 rows x 8 b x 192 k.
// Lane = (kq 0..3, bl 0..7): 9 rows x 1 batch x 48 k per lane, f32x2 FMA.
#define NBLK1 128
#define GR_   16
#define GB_   8
#define UPC_  24     // units per CTA
#define RPC_  72     // gate rows per CTA (3*UPC)
#define BPC_  8      // batches per CTA
// SMEM strides (floats): k stored in 4 chunks of 96 (+4 pad)
#define SK_   100
#define SB_   420
#define WROW_ 420

__device__ __forceinline__ unsigned long long fma2_(
    unsigned long long a, unsigned long long b, unsigned long long c)
{
    unsigned long long d;
    asm("fma.rn.f32x2 %0, %1, %2, %3;" : "=l"(d) : "l"(a), "l"(b), "l"(c));
    return d;
}

// ---------------------------------------------------------------------------
// Kernel 1: GRU1 (C=20 -> H1=384), persistent, per-batch-group grid barrier.
// ---------------------------------------------------------------------------
__global__ __launch_bounds__(512, 1) void gru1_kernel(
    const float* __restrict__ x, const float* __restrict__ h1_in,
    const float* __restrict__ Wih1, const float* __restrict__ Whh1,
    const float* __restrict__ bih1, const float* __restrict__ bhh1,
    float* __restrict__ out_h1f)
{
    extern __shared__ float sm[];
    float* h_s  = sm;                       // BPC*SB   = 3360
    float* Wh_s = h_s  + BPC_*SB_;          // RPC*WROW = 30240
    float* xs   = Wh_s + RPC_*WROW_;        // BPC*20   = 160
    float* Wi_s = xs   + BPC_*C_;           // RPC*20   = 1440
    float* bi_s = Wi_s + RPC_*C_;           // 72
    float* bh_s = bi_s + RPC_;              // 72
    float* red  = bh_s + RPC_;              // 16*72 = 1152

    const int tid  = threadIdx.x;
    const int lane = tid & 31;
    const int w    = tid >> 5;                 // 0..15
    const int rg   = blockIdx.x & (GR_-1);     // row group 0..15
    const int bg   = blockIdx.x >> 4;          // batch group 0..7
    const int u0   = rg * UPC_;                // first global hidden unit
    const int b0c  = bg * BPC_;                // first global batch

    const int rgrp  = w >> 1;                  // 0..7 -> units rgrp*3..+2
    const int khalf = w & 1;                   // 0..1 -> k 0..191 / 192..383
    const int kq    = lane >> 3;               // k sub-quarter within half
    const int bl    = lane & 7;                // batch 0..7

    // ---- load recurrent weights into SMEM (chunked-k layout) ----
    for (int i = tid; i < RPC_*H1_; i += 512) {
        int lr = i / H1_, k = i % H1_;
        int g = lr / UPC_, ul = lr % UPC_;
        Wh_s[lr*WROW_ + (k/96)*SK_ + (k%96)] =
            Whh1[(size_t)(g*H1_ + u0 + ul)*H1_ + k];
    }
    for (int i = tid; i < RPC_*C_; i += 512) {
        int lr = i / C_, c = i % C_;
        int g = lr / UPC_, ul = lr % UPC_;
        Wi_s[i] = Wih1[(g*H1_ + u0 + ul)*C_ + c];
    }
    if (tid < RPC_) {
        int g = tid / UPC_, ul = tid % UPC_;
        bi_s[tid] = bih1[g*H1_ + u0 + ul];
        bh_s[tid] = bhh1[g*H1_ + u0 + ul];
    }

    // Barrier generation base (stable: previous launch finished; nobody
    // writes g_bar_gen[bg] until all 16 CTAs of this bg arrive at step 0).
    const unsigned base = *(volatile unsigned*)&g_bar_gen[bg];

    // per-lane k base: global k = khalf*192 + kq*48 + [0..47]
    const int c0  = khalf*2 + (kq >> 1);       // 96-chunk index
    const int off = (kq & 1) * 48;
    const float* hb = h_s  + bl*SB_ + c0*SK_ + off;
    const float* wb = Wh_s + (rgrp*3)*WROW_ + c0*SK_ + off;

    // epilogue identity (t-invariant)
    const bool epi = (khalf == 0) && (lane < 24);
    const int  eu   = lane >> 3;               // 0..2
    const int  ebl  = lane & 7;
    const int  eb   = b0c + ebl;               // global batch
    const int  eul  = rgrp*3 + eu;             // local unit 0..23
    const int  eug  = u0 + eul;                // global hidden unit
    float hn_prev = 0.f;

    for (int t = 0; t < L_; t++) {
        // ---- deferred y1 store from previous step (overlaps h load) ----
        if (t > 0 && epi)
            g_y1[((size_t)eb*L_ + (t-1))*H1_ + eug] = hn_prev;

        // ---- load h state for our 8 batches (L2, bypass L1) ----
        {
            const float4* s4 = (t == 0)
                ? (const float4*)(h1_in + b0c*H1_)
                : (const float4*)(g_h1  + b0c*H1_);
            #pragma unroll 1
            for (int i4 = tid; i4 < BPC_*(H1_/4); i4 += 512) {
                int b = i4 / 96, k4 = i4 % 96;
                float4 v = (t == 0) ? __ldg(s4 + i4) : __ldcg(s4 + i4);
                *((float4*)h_s + (size_t)b*(SB_/4) + (k4/24)*(SK_/4) + (k4%24)) = v;
            }
        }
        // ---- x_t for our batches (8 x 20) ----
        if (tid < BPC_*5) {
            int b = tid / 5, c4 = tid % 5;
            ((float4*)(xs + b*C_))[c4] =
                __ldg((const float4*)(x + ((size_t)(b0c + b)*L_ + t)*C_) + c4);
        }
        __syncthreads();

        // ---- recurrent GEMM: 9 rows x 1 batch x 48 k per lane, f32x2 ----
        unsigned long long acc[9];
        #pragma unroll
        for (int r = 0; r < 9; r++) acc[r] = 0ull;

        #pragma unroll
        for (int j = 0; j < 12; j++) {
            const ulonglong2 h2 = *(const ulonglong2*)(hb + 4*j);
            #pragma unroll
            for (int g = 0; g < 3; g++) {
                #pragma unroll
                for (int u = 0; u < 3; u++) {
                    const ulonglong2 w2 =
                        *(const ulonglong2*)(wb + (g*UPC_ + u)*WROW_ + 4*j);
                    const int r = g*3 + u;
                    acc[r] = fma2_(w2.x, h2.x, acc[r]);
                    acc[r] = fma2_(w2.y, h2.y, acc[r]);
                }
            }
        }
        // unpack f32x2 partial sums, reduce over kq (lane bits 3,4)
        float s[9];
        #pragma unroll
        for (int r = 0; r < 9; r++) {
            float lo, hi;
            asm("mov.b64 {%0,%1}, %2;" : "=f"(lo), "=f"(hi) : "l"(acc[r]));
            s[r] = lo + hi;
        }
        #pragma unroll
        for (int r = 0; r < 9; r++) {
            s[r] += __shfl_xor_sync(0xffffffffu, s[r], 8);
            s[r] += __shfl_xor_sync(0xffffffffu, s[r], 16);
        }
        if (kq == 0) {
            #pragma unroll
            for (int r = 0; r < 9; r++) red[w*72 + r*8 + bl] = s[r];
        }
        __syncthreads();   // cross-warp (khalf) combine

        // ---- epilogue: khalf==0 warps, 24 lanes = 3 units x 8 batches ----
        if (epi) {
            float xr = bi_s[eul], xz = bi_s[UPC_+eul], xn = bi_s[2*UPC_+eul];
            #pragma unroll
            for (int c = 0; c < C_; c++) {
                float xv = xs[ebl*C_ + c];
                xr = fmaf(Wi_s[eul*C_ + c],            xv, xr);
                xz = fmaf(Wi_s[(UPC_+eul)*C_ + c],     xv, xz);
                xn = fmaf(Wi_s[(2*UPC_+eul)*C_ + c],   xv, xn);
            }
            const int w0 = rgrp*2, w1 = rgrp*2 + 1;
            float ghr = red[w0*72 + (eu  )*8 + ebl] + red[w1*72 + (eu  )*8 + ebl] + bh_s[eul];
            float ghz = red[w0*72 + (3+eu)*8 + ebl] + red[w1*72 + (3+eu)*8 + ebl] + bh_s[UPC_+eul];
            float ghn = red[w0*72 + (6+eu)*8 + ebl] + red[w1*72 + (6+eu)*8 + ebl] + bh_s[2*UPC_+eul];
            float rgt = 1.f / (1.f + __expf(-(xr + ghr)));
            float zgt = 1.f / (1.f + __expf(-(xz + ghz)));
            float ngt = tanhf(xn + rgt * ghn);
            float hold = h_s[ebl*SB_ + (eug/96)*SK_ + (eug%96)];
            float hn = (1.f - zgt) * ngt + zgt * hold;
            g_h1[eb*H1_ + eug] = hn;        // must be visible before barrier
            hn_prev = hn;                   // y1 store deferred to next step
            if (t == L_-1) {
                out_h1f[eb*H1_ + eug] = hn;
                g_y1[((size_t)eb*L_ + t)*H1_ + eug] = hn;
            }
        }

        // ---- per-batch-group grid barrier (16 CTAs) ----
        __threadfence();
        __syncthreads();
        if (tid == 0) {
            unsigned a = atomicAdd(&g_bar_cnt[bg], 1u);
            if (a == GR_ - 1) {
                g_bar_cnt[bg] = 0;
                __threadfence();
                *(volatile unsigned*)&g_bar_gen[bg] = base + (unsigned)(t + 1);
            } else {
                while (*(volatile unsigned*)&g_bar_gen[bg] - base < (unsigned)(t + 1))
                    __nanosleep(16);
            }
        }
        __syncthreads();
    }
}

// ---------------------------------------------------------------------------
// Kernel 2: GRU2 (H1=384 -> H2=16) + ReLU + dual-FC (== 2*tanh(fc)) -> x_mid.
// One CTA per batch element; all weights SMEM-resident; y1 prefetched 1 step.
// ---------------------------------------------------------------------------
__global__ __launch_bounds__(256, 1) void gru2_kernel(
    const float* __restrict__ h2_in,
    const float* __restrict__ Wih2, const float* __restrict__ Whh2,
    const float* __restrict__ bih2, const float* __restrict__ bhh2,
    const float* __restrict__ Wfc,  const float* __restrict__ bfc,
    float* __restrict__ out)
{
    extern __shared__ float sm[];
    float* W2  = sm;                 // 48*384 = 18432
    float* Wh  = W2  + 48*H1_;       // 48*16  = 768
    float* Wf  = Wh  + 48*H2_;       // 20*16  = 320
    float* bi  = Wf  + F_*H2_;       // 48
    float* bh  = bi  + 48;           // 48
    float* bf  = bh  + 48;           // 20
    float* ys  = bf  + 20;           // 2*384  = 768 (double buffer)
    float* ihp = ys  + 2*H1_;        // 48
    float* h2s = ihp + 48;           // 16
    float* y2s = h2s + 16;           // 16

    const int tid = threadIdx.x, lane = tid & 31, w = tid >> 5;
    const int b = blockIdx.x;

    for (int i = tid; i < 48*H1_; i += 256) W2[i] = Wih2[i];
    for (int i = tid; i < 48*H2_; i += 256) Wh[i] = Whh2[i];
    for (int i = tid; i < F_*H2_; i += 256) Wf[i] = Wfc[i];
    if (tid < 48) { bi[tid] = bih2[tid]; bh[tid] = bhh2[tid]; }
    if (tid < 20) bf[tid] = bfc[tid];
    if (tid < 16) h2s[tid] = h2_in[b*H2_ + tid];

    const float* y1p = g_y1 + (size_t)b*L_*H1_;
    for (int i = tid; i < 96; i += 256)
        ((float4*)ys)[i] = __ldg((const float4*)y1p + i);
    __syncthreads();

    const int row0 = w * 6;
    for (int t = 0; t < L_; t++) {
        float* cur = ys + (t & 1) * H1_;
        float* nxt = ys + ((t + 1) & 1) * H1_;
        float4 pf;
        bool dopf = (tid < 96) && (t + 1 < L_);
        if (dopf) pf = __ldg((const float4*)(y1p + (size_t)(t + 1)*H1_) + tid);

        // input projection: 6 rows/warp, K split over lanes
        float acc[6] = {0,0,0,0,0,0};
        #pragma unroll 1
        for (int kk = 0; kk < 12; kk++) {
            int k = (kk << 5) + lane;
            float yv = cur[k];
            #pragma unroll
            for (int r = 0; r < 6; r++)
                acc[r] = fmaf(W2[(row0 + r)*H1_ + k], yv, acc[r]);
        }
        #pragma unroll
        for (int s = 16; s > 0; s >>= 1) {
            #pragma unroll
            for (int r = 0; r < 6; r++)
                acc[r] += __shfl_xor_sync(0xffffffffu, acc[r], s);
        }
        #pragma unroll
        for (int r = 0; r < 6; r++)
            if (lane == r) ihp[row0 + r] = acc[r] + bi[row0 + r];
        if (dopf) ((float4*)nxt)[tid] = pf;
        __syncthreads();

        if (w == 0) {
            float hn = 0.f;
            if (lane < 16) {
                float ghr = bh[lane], ghz = bh[16+lane], ghn = bh[32+lane];
                #pragma unroll
                for (int k = 0; k < 16; k++) {
                    float hv = h2s[k];
                    ghr = fmaf(Wh[lane*16 + k],      hv, ghr);
                    ghz = fmaf(Wh[(16+lane)*16 + k], hv, ghz);
                    ghn = fmaf(Wh[(32+lane)*16 + k], hv, ghn);
                }
                float rg = 1.f / (1.f + __expf(-(ihp[lane] + ghr)));
                float zg = 1.f / (1.f + __expf(-(ihp[16+lane] + ghz)));
                float ng = tanhf(ihp[32+lane] + rg * ghn);
                hn = (1.f - zg) * ng + zg * h2s[lane];
            }
            __syncwarp();
            if (lane < 16) { h2s[lane] = hn; y2s[lane] = fmaxf(hn, 0.f); }
            __syncwarp();
            if (lane < 20) {
                float a = bf[lane];
                #pragma unroll
                for (int k = 0; k < 16; k++)
                    a = fmaf(Wf[lane*16 + k], y2s[k], a);
                out[XMID_OFF + ((size_t)b*L_ + t)*F_ + lane] = 2.f * tanhf(a);
            }
            if (t == L_-1 && lane < 16) out[H2F_OFF + b*H2_ + lane] = hn;
        }
        __syncthreads();
    }
}

// ---------------------------------------------------------------------------
// Kernel 3: GRU3 (F=20 -> F=20) on time-reversed x_mid, x_out = tanh(y3).
// One warp per batch element.
// ---------------------------------------------------------------------------
__global__ __launch_bounds__(32, 1) void gru3_kernel(
    const float* __restrict__ h3_in,
    const float* __restrict__ Wih3, const float* __restrict__ Whh3,
    const float* __restrict__ bih3, const float* __restrict__ bhh3,
    float* __restrict__ out)
{
    __shared__ float Wi[60*20], Wh[60*20];
    __shared__ float bi[60], bh[60], as_[60], gs_[60], h3s[20];
    __shared__ __align__(16) float ins[2][20];

    const int lane = threadIdx.x;
    const int b = blockIdx.x;

    for (int i = lane; i < 60*20; i += 32) { Wi[i] = Wih3[i]; Wh[i] = Whh3[i]; }
    for (int i = lane; i < 60;    i += 32) { bi[i] = bih3[i]; bh[i] = bhh3[i]; }
    if (lane < 20) h3s[lane] = h3_in[b*F_ + lane];

    const float* xmid = out + XMID_OFF + (size_t)b*L_*F_;
    if (lane < 5)
        ((float4*)ins[0])[lane] = *((const float4*)(xmid + (size_t)(L_-1)*F_) + lane);
    __syncwarp();

    for (int t = 0; t < L_; t++) {
        float* in = ins[t & 1];
        float4 pf;
        bool dopf = (lane < 5) && (t + 1 < L_);
        if (dopf)
            pf = *((const float4*)(xmid + (size_t)(L_-2-t)*F_) + lane);

        const int r1 = lane + 32;
        const bool has1 = (r1 < 60);
        float a0 = bi[lane], g0 = bh[lane], a1 = 0.f, g1 = 0.f;
        if (has1) { a1 = bi[r1]; g1 = bh[r1]; }
        #pragma unroll
        for (int k = 0; k < 20; k++) {
            float iv = in[k], hv = h3s[k];
            a0 = fmaf(Wi[lane*20 + k], iv, a0);
            g0 = fmaf(Wh[lane*20 + k], hv, g0);
            if (has1) {
                a1 = fmaf(Wi[r1*20 + k], iv, a1);
                g1 = fmaf(Wh[r1*20 + k], hv, g1);
            }
        }
        as_[lane] = a0; gs_[lane] = g0;
        if (has1) { as_[r1] = a1; gs_[r1] = g1; }
        __syncwarp();

        float hn = 0.f;
        if (lane < 20) {
            float rg = 1.f / (1.f + __expf(-(as_[lane] + gs_[lane])));
            float zg = 1.f / (1.f + __expf(-(as_[20+lane] + gs_[20+lane])));
            float ng = tanhf(as_[40+lane] + rg * gs_[40+lane]);
            hn = (1.f - zg) * ng + zg * h3s[lane];
        }
        __syncwarp();
        if (lane < 20) {
            h3s[lane] = hn;
            out[XOUT_OFF + ((size_t)b*L_ + t)*F_ + lane] = tanhf(hn);
        }
        if (dopf) ((float4*)ins[(t + 1) & 1])[lane] = pf;
        __syncwarp();
    }
    if (lane < 20) out[H3F_OFF + b*F_ + lane] = h3s[lane];
}

// ---------------------------------------------------------------------------
extern "C" void kernel_launch(void* const* d_in, const int* in_sizes, int n_in,
                              void* d_out, int out_size)
{
    const float* x    = (const float*)d_in[0];
    const float* h1   = (const float*)d_in[1];
    const float* h2   = (const float*)d_in[2];
    const float* h3   = (const float*)d_in[3];
    const float* Wih1 = (const float*)d_in[4];
    const float* Whh1 = (const float*)d_in[5];
    const float* bih1 = (const float*)d_in[6];
    const float* bhh1 = (const float*)d_in[7];
    const float* Wih2 = (const float*)d_in[8];
    const float* Whh2 = (const float*)d_in[9];
    const float* bih2 = (const float*)d_in[10];
    const float* bhh2 = (const float*)d_in[11];
    const float* Wih3 = (const float*)d_in[12];
    const float* Whh3 = (const float*)d_in[13];
    const float* bih3 = (const float*)d_in[14];
    const float* bhh3 = (const float*)d_in[15];
    const float* Wfc  = (const float*)d_in[16];
    const float* bfc  = (const float*)d_in[17];
    float* out = (float*)d_out;

    const int SMEM1 = (BPC_*SB_ + RPC_*WROW_ + BPC_*C_ + RPC_*C_ + RPC_ + RPC_ + 16*72) * 4;
    const int SMEM2 = (48*H1_ + 48*H2_ + F_*H2_ + 48 + 48 + 20 + 2*H1_ + 48 + 16 + 16) * 4;
    cudaFuncSetAttribute(gru1_kernel, cudaFuncAttributeMaxDynamicSharedMemorySize, SMEM1);
    cudaFuncSetAttribute(gru2_kernel, cudaFuncAttributeMaxDynamicSharedMemorySize, SMEM2);

    gru1_kernel<<<NBLK1, 512, SMEM1>>>(x, h1, Wih1, Whh1, bih1, bhh1, out + H1F_OFF);
    gru2_kernel<<<B_, 256, SMEM2>>>(h2, Wih2, Whh2, bih2, bhh2, Wfc, bfc, out);
    gru3_kernel<<<B_, 32>>>(h3, Wih3, Whh3, bih3, bhh3, out);
}

// round 14
// speedup vs baseline: 2.0772x; 1.1070x over previous
#include <cuda_runtime.h>
#include <cstddef>

// Problem constants
#define B_  64
#define L_  2048
#define C_  20
#define H1_ 384
#define H2_ 16
#define F_  20

// Output layout (flattened tuple, reference order):
// x_mid (B,L,F) | x_out (B,L,F) | h1f (B,H1) | h2f (B,H2) | h3f (B,F)
#define XMID_OFF 0
#define XOUT_OFF (B_*L_*F_)
#define H1F_OFF  (2*B_*L_*F_)
#define H2F_OFF  (H1F_OFF + B_*H1_)
#define H3F_OFF  (H2F_OFF + B_*H2_)

// Scratch (device globals: allocation-free rule)
__device__ float g_h1[B_*H1_];
__device__ float g_y1[(size_t)B_*L_*H1_];        // 201 MB
__device__ float g_xp[(size_t)B_*L_*48];         // 25 MB (gru2 input proj)
__device__ unsigned g_bar_cnt[8];                // per-batch-group
__device__ unsigned g_bar_gen[8];                // monotonic across launches

// GRU1 partition: 32 row-groups x 8 batch-groups = 256 CTAs, 2 per SM.
// Each CTA: 12 hidden units (36 gate rows, SMEM-resident) x 8 batches.
// 256 threads = 8 warps = 4 rgrp x 2 khalf. Warp tile: 9 rows x 8 b x 192 k.
// Lane = (kq 0..3, bl 0..7): 9 rows x 1 batch x 48 k per lane, f32x2 FMA.
#define NBLK1 256
#define GR_   32
#define GB_   8
#define UPC_  12     // units per CTA
#define RPC_  36     // gate rows per CTA (3*UPC)
#define BPC_  8      // batches per CTA
// SMEM strides (floats): k stored in 4 chunks of 96 (+4 pad)
#define SK_   100
#define SB_   420
#define WROW_ 420

__device__ __forceinline__ unsigned long long fma2_(
    unsigned long long a, unsigned long long b, unsigned long long c)
{
    unsigned long long d;
    asm("fma.rn.f32x2 %0, %1, %2, %3;" : "=l"(d) : "l"(a), "l"(b), "l"(c));
    return d;
}

// ---------------------------------------------------------------------------
// Kernel 1: GRU1 (C=20 -> H1=384), persistent, per-batch-group grid barrier.
// 2 CTAs (different batch groups) per SM -> independent chains hide latency.
// ---------------------------------------------------------------------------
__global__ __launch_bounds__(256, 2) void gru1_kernel(
    const float* __restrict__ x, const float* __restrict__ h1_in,
    const float* __restrict__ Wih1, const float* __restrict__ Whh1,
    const float* __restrict__ bih1, const float* __restrict__ bhh1,
    float* __restrict__ out_h1f)
{
    extern __shared__ float sm[];
    float* h_s  = sm;                       // BPC*SB   = 3360
    float* Wh_s = h_s  + BPC_*SB_;          // RPC*WROW = 15120
    float* xs   = Wh_s + RPC_*WROW_;        // BPC*20   = 160
    float* Wi_s = xs   + BPC_*C_;           // RPC*20   = 720
    float* bi_s = Wi_s + RPC_*C_;           // 36
    float* bh_s = bi_s + RPC_;              // 36
    float* red  = bh_s + RPC_;              // 8*72 = 576

    const int tid  = threadIdx.x;
    const int lane = tid & 31;
    const int w    = tid >> 5;                 // 0..7
    const int rg   = blockIdx.x >> 3;          // row group 0..31
    const int bg   = blockIdx.x & 7;           // batch group 0..7
    const int u0   = rg * UPC_;                // first global hidden unit
    const int b0c  = bg * BPC_;                // first global batch

    const int rgrp  = w >> 1;                  // 0..3 -> units rgrp*3..+2
    const int khalf = w & 1;                   // 0..1 -> k 0..191 / 192..383
    const int kq    = lane >> 3;               // k sub-quarter within half
    const int bl    = lane & 7;                // batch 0..7

    // ---- load recurrent weights into SMEM (chunked-k layout) ----
    for (int i = tid; i < RPC_*H1_; i += 256) {
        int lr = i / H1_, k = i % H1_;
        int g = lr / UPC_, ul = lr % UPC_;
        Wh_s[lr*WROW_ + (k/96)*SK_ + (k%96)] =
            Whh1[(size_t)(g*H1_ + u0 + ul)*H1_ + k];
    }
    for (int i = tid; i < RPC_*C_; i += 256) {
        int lr = i / C_, c = i % C_;
        int g = lr / UPC_, ul = lr % UPC_;
        Wi_s[i] = Wih1[(g*H1_ + u0 + ul)*C_ + c];
    }
    if (tid < RPC_) {
        int g = tid / UPC_, ul = tid % UPC_;
        bi_s[tid] = bih1[g*H1_ + u0 + ul];
        bh_s[tid] = bhh1[g*H1_ + u0 + ul];
    }

    // Barrier generation base (stable: previous launch finished; nobody
    // writes g_bar_gen[bg] until all 32 CTAs of this bg arrive at step 0).
    const unsigned base = *(volatile unsigned*)&g_bar_gen[bg];

    // per-lane k base: global k = khalf*192 + kq*48 + [0..47]
    const int c0  = khalf*2 + (kq >> 1);       // 96-chunk index
    const int off = (kq & 1) * 48;
    const float* hb = h_s  + bl*SB_ + c0*SK_ + off;
    const float* wb = Wh_s + (rgrp*3)*WROW_ + c0*SK_ + off;

    // epilogue identity (t-invariant)
    const bool epi = (khalf == 0) && (lane < 24);
    const int  eu   = lane >> 3;               // 0..2
    const int  ebl  = lane & 7;
    const int  eb   = b0c + ebl;               // global batch
    const int  eul  = rgrp*3 + eu;             // local unit 0..11
    const int  eug  = u0 + eul;                // global hidden unit
    float hn_prev = 0.f;

    for (int t = 0; t < L_; t++) {
        // ---- deferred y1 store from previous step (overlaps h load) ----
        if (t > 0 && epi)
            g_y1[((size_t)eb*L_ + (t-1))*H1_ + eug] = hn_prev;

        // ---- load h state for our 8 batches (L2, bypass L1) ----
        {
            const float4* s4 = (t == 0)
                ? (const float4*)(h1_in + b0c*H1_)
                : (const float4*)(g_h1  + b0c*H1_);
            #pragma unroll 1
            for (int i4 = tid; i4 < BPC_*(H1_/4); i4 += 256) {
                int b = i4 / 96, k4 = i4 % 96;
                float4 v = (t == 0) ? __ldg(s4 + i4) : __ldcg(s4 + i4);
                *((float4*)h_s + (size_t)b*(SB_/4) + (k4/24)*(SK_/4) + (k4%24)) = v;
            }
        }
        // ---- x_t for our batches (8 x 20) ----
        if (tid < BPC_*5) {
            int b = tid / 5, c4 = tid % 5;
            ((float4*)(xs + b*C_))[c4] =
                __ldg((const float4*)(x + ((size_t)(b0c + b)*L_ + t)*C_) + c4);
        }
        __syncthreads();

        // ---- recurrent GEMM: 9 rows x 1 batch x 48 k per lane, f32x2 ----
        unsigned long long acc[9];
        #pragma unroll
        for (int r = 0; r < 9; r++) acc[r] = 0ull;

        #pragma unroll
        for (int j = 0; j < 12; j++) {
            const ulonglong2 h2 = *(const ulonglong2*)(hb + 4*j);
            #pragma unroll
            for (int g = 0; g < 3; g++) {
                #pragma unroll
                for (int u = 0; u < 3; u++) {
                    const ulonglong2 w2 =
                        *(const ulonglong2*)(wb + (g*UPC_ + u)*WROW_ + 4*j);
                    const int r = g*3 + u;
                    acc[r] = fma2_(w2.x, h2.x, acc[r]);
                    acc[r] = fma2_(w2.y, h2.y, acc[r]);
                }
            }
        }
        // unpack f32x2 partial sums, reduce over kq (lane bits 3,4)
        float s[9];
        #pragma unroll
        for (int r = 0; r < 9; r++) {
            float lo, hi;
            asm("mov.b64 {%0,%1}, %2;" : "=f"(lo), "=f"(hi) : "l"(acc[r]));
            s[r] = lo + hi;
        }
        #pragma unroll
        for (int r = 0; r < 9; r++) {
            s[r] += __shfl_xor_sync(0xffffffffu, s[r], 8);
            s[r] += __shfl_xor_sync(0xffffffffu, s[r], 16);
        }
        if (kq == 0) {
            #pragma unroll
            for (int r = 0; r < 9; r++) red[w*72 + r*8 + bl] = s[r];
        }
        __syncthreads();   // cross-warp (khalf) combine

        // ---- epilogue: khalf==0 warps, 24 lanes = 3 units x 8 batches ----
        if (epi) {
            float xr = bi_s[eul], xz = bi_s[UPC_+eul], xn = bi_s[2*UPC_+eul];
            #pragma unroll
            for (int c = 0; c < C_; c++) {
                float xv = xs[ebl*C_ + c];
                xr = fmaf(Wi_s[eul*C_ + c],            xv, xr);
                xz = fmaf(Wi_s[(UPC_+eul)*C_ + c],     xv, xz);
                xn = fmaf(Wi_s[(2*UPC_+eul)*C_ + c],   xv, xn);
            }
            const int w0 = rgrp*2, w1 = rgrp*2 + 1;
            float ghr = red[w0*72 + (eu  )*8 + ebl] + red[w1*72 + (eu  )*8 + ebl] + bh_s[eul];
            float ghz = red[w0*72 + (3+eu)*8 + ebl] + red[w1*72 + (3+eu)*8 + ebl] + bh_s[UPC_+eul];
            float ghn = red[w0*72 + (6+eu)*8 + ebl] + red[w1*72 + (6+eu)*8 + ebl] + bh_s[2*UPC_+eul];
            float rgt = 1.f / (1.f + __expf(-(xr + ghr)));
            float zgt = 1.f / (1.f + __expf(-(xz + ghz)));
            float ngt = tanhf(xn + rgt * ghn);
            float hold = h_s[ebl*SB_ + (eug/96)*SK_ + (eug%96)];
            float hn = (1.f - zgt) * ngt + zgt * hold;
            g_h1[eb*H1_ + eug] = hn;        // must be visible before barrier
            hn_prev = hn;                   // y1 store deferred to next step
            if (t == L_-1) {
                out_h1f[eb*H1_ + eug] = hn;
                g_y1[((size_t)eb*L_ + t)*H1_ + eug] = hn;
            }
        }

        // ---- per-batch-group grid barrier (32 CTAs) ----
        __threadfence();
        __syncthreads();
        if (tid == 0) {
            unsigned a = atomicAdd(&g_bar_cnt[bg], 1u);
            if (a == GR_ - 1) {
                g_bar_cnt[bg] = 0;
                __threadfence();
                *(volatile unsigned*)&g_bar_gen[bg] = base + (unsigned)(t + 1);
            } else {
                while (*(volatile unsigned*)&g_bar_gen[bg] - base < (unsigned)(t + 1))
                    __nanosleep(16);
            }
        }
        __syncthreads();
    }
}

// ---------------------------------------------------------------------------
// Kernel 2a: gru2 input projection xp = y1 @ Wih2^T + bih2  (time-parallel).
// Each warp processes 4 (b,t) rows per iteration; W in SMEM.
// ---------------------------------------------------------------------------
__global__ __launch_bounds__(256) void gru2a_kernel(
    const float* __restrict__ Wih2, const float* __restrict__ bih2)
{
    extern __shared__ float sm[];
    float* W2s = sm;                 // 48*384 = 18432
    float* bis = W2s + 48*H1_;       // 48
    float* xps = bis + 48;           // 8 warps * 4 rows * 48 = 1536

    const int tid = threadIdx.x, lane = tid & 31, w = tid >> 5;

    for (int i = tid; i < 48*H1_; i += 256) W2s[i] = Wih2[i];
    if (tid < 48) bis[tid] = bih2[tid];
    __syncthreads();

    const int nquad = (B_*L_) / 4;                 // 32768
    const int gw    = blockIdx.x*8 + w;            // global warp id
    const int nw    = gridDim.x*8;

    for (int q = gw; q < nquad; q += nw) {
        const int row0 = q * 4;
        // load 4 rows of y1: lane covers k = 4*lane + {0..3} + 128*j
        float4 y[4][3];
        #pragma unroll
        for (int r = 0; r < 4; r++) {
            const float4* yr = (const float4*)(g_y1 + (size_t)(row0 + r)*H1_);
            y[r][0] = __ldg(yr + lane);
            y[r][1] = __ldg(yr + 32 + lane);
            y[r][2] = __ldg(yr + 64 + lane);
        }
        for (int g = 0; g < 48; g++) {
            const float* wr = W2s + g*H1_;
            const float4 w0 = *(const float4*)(wr + 4*lane);
            const float4 w1 = *(const float4*)(wr + 128 + 4*lane);
            const float4 w2 = *(const float4*)(wr + 256 + 4*lane);
            #pragma unroll
            for (int r = 0; r < 4; r++) {
                float s = w0.x*y[r][0].x + w0.y*y[r][0].y
                        + w0.z*y[r][0].z + w0.w*y[r][0].w;
                s = fmaf(w1.x, y[r][1].x, s); s = fmaf(w1.y, y[r][1].y, s);
                s = fmaf(w1.z, y[r][1].z, s); s = fmaf(w1.w, y[r][1].w, s);
                s = fmaf(w2.x, y[r][2].x, s); s = fmaf(w2.y, y[r][2].y, s);
                s = fmaf(w2.z, y[r][2].z, s); s = fmaf(w2.w, y[r][2].w, s);
                #pragma unroll
                for (int d = 16; d > 0; d >>= 1)
                    s += __shfl_xor_sync(0xffffffffu, s, d);
                if (lane == (g & 31)) xps[(w*4 + r)*48 + g] = s + bis[g];
            }
        }
        __syncwarp();
        #pragma unroll
        for (int r = 0; r < 4; r++)
            if (lane < 12)
                ((float4*)&g_xp[(size_t)(row0 + r)*48])[lane] =
                    ((float4*)&xps[(w*4 + r)*48])[lane];
        __syncwarp();
    }
}

// ---------------------------------------------------------------------------
// Kernel 2b: gru2 recurrence (H2=16) + ReLU + dual-FC -> x_mid.
// One warp per batch; h in registers; shuffle broadcasts; xp ring prefetch.
// ---------------------------------------------------------------------------
__global__ __launch_bounds__(32) void gru2b_kernel(
    const float* __restrict__ h2_in,
    const float* __restrict__ Whh2, const float* __restrict__ bhh2,
    const float* __restrict__ Wfc,  const float* __restrict__ bfc,
    float* __restrict__ out)
{
    __shared__ float Wh[48*16], Wf[20*16], bh[48], bf[20];
    __shared__ __align__(16) float ring[4][48];

    const int lane = threadIdx.x;
    const int b = blockIdx.x;
    const int r0 = lane & 15;
    const int fr = (lane < 20) ? lane : 0;

    for (int i = lane; i < 48*16; i += 32) Wh[i] = Whh2[i];
    for (int i = lane; i < 20*16; i += 32) Wf[i] = Wfc[i];
    for (int i = lane; i < 48;    i += 32) bh[i] = bhh2[i];
    if (lane < 20) bf[lane] = bfc[lane];

    float h = (lane < 16) ? h2_in[b*H2_ + lane] : 0.f;

    const float* xpb = g_xp + (size_t)b*L_*48;
    if (lane < 24) {   // prime rows 0,1
        int r = lane / 12, c = lane % 12;
        ((float4*)ring[r])[c] = __ldg((const float4*)(xpb + r*48) + c);
    }
    __syncwarp();

    for (int t = 0; t < L_; t++) {
        float4 pf;
        const bool dp = (lane < 12) && (t + 2 < L_);
        if (dp) pf = __ldg((const float4*)(xpb + (size_t)(t + 2)*48) + lane);

        const float* cur = ring[t & 3];

        float ghr = bh[r0], ghz = bh[16 + r0], ghn = bh[32 + r0];
        #pragma unroll
        for (int k = 0; k < 16; k++) {
            float hv = __shfl_sync(0xffffffffu, h, k);
            ghr = fmaf(Wh[r0*16 + k],        hv, ghr);
            ghz = fmaf(Wh[(16+r0)*16 + k],   hv, ghz);
            ghn = fmaf(Wh[(32+r0)*16 + k],   hv, ghn);
        }
        float rg = 1.f / (1.f + __expf(-(cur[r0]      + ghr)));
        float zg = 1.f / (1.f + __expf(-(cur[16 + r0] + ghz)));
        float ng = tanhf(cur[32 + r0] + rg * ghn);
        float hn = (1.f - zg) * ng + zg * h;
        if (lane < 16) h = hn;
        float y2 = fmaxf(hn, 0.f);

        float a = bf[fr];
        #pragma unroll
        for (int k = 0; k < 16; k++) {
            float yv = __shfl_sync(0xffffffffu, y2, k);
            a = fmaf(Wf[fr*16 + k], yv, a);
        }
        if (lane < 20)
            out[XMID_OFF + ((size_t)b*L_ + t)*F_ + lane] = 2.f * tanhf(a);

        if (dp) ((float4*)ring[(t + 2) & 3])[lane] = pf;
        __syncwarp();
    }
    if (lane < 16) out[H2F_OFF + b*H2_ + lane] = h;
}

// ---------------------------------------------------------------------------
// Kernel 3: GRU3 (F=20 -> F=20) on time-reversed x_mid, x_out = tanh(y3).
// One warp per batch element.
// ---------------------------------------------------------------------------
__global__ __launch_bounds__(32) void gru3_kernel(
    const float* __restrict__ h3_in,
    const float* __restrict__ Wih3, const float* __restrict__ Whh3,
    const float* __restrict__ bih3, const float* __restrict__ bhh3,
    float* __restrict__ out)
{
    __shared__ float Wi[60*20], Wh[60*20];
    __shared__ float bi[60], bh[60], as_[60], gs_[60], h3s[20];
    __shared__ __align__(16) float ins[2][20];

    const int lane = threadIdx.x;
    const int b = blockIdx.x;

    for (int i = lane; i < 60*20; i += 32) { Wi[i] = Wih3[i]; Wh[i] = Whh3[i]; }
    for (int i = lane; i < 60;    i += 32) { bi[i] = bih3[i]; bh[i] = bhh3[i]; }
    if (lane < 20) h3s[lane] = h3_in[b*F_ + lane];

    const float* xmid = out + XMID_OFF + (size_t)b*L_*F_;
    if (lane < 5)
        ((float4*)ins[0])[lane] = *((const float4*)(xmid + (size_t)(L_-1)*F_) + lane);
    __syncwarp();

    for (int t = 0; t < L_; t++) {
        float* in = ins[t & 1];
        float4 pf;
        bool dopf = (lane < 5) && (t + 1 < L_);
        if (dopf)
            pf = *((const float4*)(xmid + (size_t)(L_-2-t)*F_) + lane);

        const int r1 = lane + 32;
        const bool has1 = (r1 < 60);
        float a0 = bi[lane], g0 = bh[lane], a1 = 0.f, g1 = 0.f;
        if (has1) { a1 = bi[r1]; g1 = bh[r1]; }
        #pragma unroll
        for (int k = 0; k < 20; k++) {
            float iv = in[k], hv = h3s[k];
            a0 = fmaf(Wi[lane*20 + k], iv, a0);
            g0 = fmaf(Wh[lane*20 + k], hv, g0);
            if (has1) {
                a1 = fmaf(Wi[r1*20 + k], iv, a1);
                g1 = fmaf(Wh[r1*20 + k], hv, g1);
            }
        }
        as_[lane] = a0; gs_[lane] = g0;
        if (has1) { as_[r1] = a1; gs_[r1] = g1; }
        __syncwarp();

        float hn = 0.f;
        if (lane < 20) {
            float rg = 1.f / (1.f + __expf(-(as_[lane] + gs_[lane])));
            float zg = 1.f / (1.f + __expf(-(as_[20+lane] + gs_[20+lane])));
            float ng = tanhf(as_[40+lane] + rg * gs_[40+lane]);
            hn = (1.f - zg) * ng + zg * h3s[lane];
        }
        __syncwarp();
        if (lane < 20) {
            h3s[lane] = hn;
            out[XOUT_OFF + ((size_t)b*L_ + t)*F_ + lane] = tanhf(hn);
        }
        if (dopf) ((float4*)ins[(t + 1) & 1])[lane] = pf;
        __syncwarp();
    }
    if (lane < 20) out[H3F_OFF + b*F_ + lane] = h3s[lane];
}

// ---------------------------------------------------------------------------
extern "C" void kernel_launch(void* const* d_in, const int* in_sizes, int n_in,
                              void* d_out, int out_size)
{
    const float* x    = (const float*)d_in[0];
    const float* h1   = (const float*)d_in[1];
    const float* h2   = (const float*)d_in[2];
    const float* h3   = (const float*)d_in[3];
    const float* Wih1 = (const float*)d_in[4];
    const float* Whh1 = (const float*)d_in[5];
    const float* bih1 = (const float*)d_in[6];
    const float* bhh1 = (const float*)d_in[7];
    const float* Wih2 = (const float*)d_in[8];
    const float* Whh2 = (const float*)d_in[9];
    const float* bih2 = (const float*)d_in[10];
    const float* bhh2 = (const float*)d_in[11];
    const float* Wih3 = (const float*)d_in[12];
    const float* Whh3 = (const float*)d_in[13];
    const float* bih3 = (const float*)d_in[14];
    const float* bhh3 = (const float*)d_in[15];
    const float* Wfc  = (const float*)d_in[16];
    const float* bfc  = (const float*)d_in[17];
    float* out = (float*)d_out;

    const int SMEM1 = (BPC_*SB_ + RPC_*WROW_ + BPC_*C_ + RPC_*C_ + RPC_ + RPC_ + 8*72) * 4;
    const int SMEM2A = (48*H1_ + 48 + 8*4*48) * 4;
    cudaFuncSetAttribute(gru1_kernel,  cudaFuncAttributeMaxDynamicSharedMemorySize, SMEM1);
    cudaFuncSetAttribute(gru2a_kernel, cudaFuncAttributeMaxDynamicSharedMemorySize, SMEM2A);

    gru1_kernel<<<NBLK1, 256, SMEM1>>>(x, h1, Wih1, Whh1, bih1, bhh1, out + H1F_OFF);
    gru2a_kernel<<<256, 256, SMEM2A>>>(Wih2, bih2);
    gru2b_kernel<<<B_, 32>>>(h2, Whh2, bhh2, Wfc, bfc, out);
    gru3_kernel<<<B_, 32>>>(h3, Wih3, Whh3, bih3, bhh3, out);
}